// round 1
// baseline (speedup 1.0000x reference)
#include <cuda_runtime.h>

// out[e,b,o] = sum_n x[e,b,n] * W[e,o,n] + b[e,o]
// E=50000, B=512, N=2, O=2 (but derived from in_sizes to stay general).
//
// Memory-bound: ~411 MB of traffic, ~205 MFLOP. One thread handles two
// (e,b) rows via a single float4 load/store. W[e] (4 floats) and b[e]
// (2 floats) are shared by 256 consecutive threads -> L1/L2 broadcast.

__global__ void plt_kernel(const float4* __restrict__ x4,
                           const float4* __restrict__ W4,
                           const float2* __restrict__ b2,
                           float4* __restrict__ out4,
                           int total_quads,
                           int log2_quads_per_edge) {
    int i = blockIdx.x * blockDim.x + threadIdx.x;
    if (i >= total_quads) return;

    int e = i >> log2_quads_per_edge;

    float4 xv = __ldg(x4 + i);   // x[e, b..b+1, 0..1]
    float4 wv = __ldg(W4 + e);   // {W[e,0,0], W[e,0,1], W[e,1,0], W[e,1,1]}
    float2 bv = __ldg(b2 + e);   // {b[e,0], b[e,1]}

    float4 o;
    o.x = fmaf(xv.x, wv.x, fmaf(xv.y, wv.y, bv.x));  // out[e,b,0]
    o.y = fmaf(xv.x, wv.z, fmaf(xv.y, wv.w, bv.y));  // out[e,b,1]
    o.z = fmaf(xv.z, wv.x, fmaf(xv.w, wv.y, bv.x));  // out[e,b+1,0]
    o.w = fmaf(xv.z, wv.z, fmaf(xv.w, wv.w, bv.y));  // out[e,b+1,1]

    out4[i] = o;
}

extern "C" void kernel_launch(void* const* d_in, const int* in_sizes, int n_in,
                              void* d_out, int out_size) {
    const float* x = (const float*)d_in[0];   // [E, B, N]
    const float* W = (const float*)d_in[1];   // [E, O, N]
    const float* b = (const float*)d_in[2];   // [E, O]

    // Derive shapes: b has E*O elements with O=2; W has E*O*N with N=2.
    int E = in_sizes[2] / 2;                      // 50000
    int per_edge = in_sizes[0] / E;               // B*N = 1024 floats per edge
    int quads_per_edge = per_edge / 4;            // 256
    // quads_per_edge is a power of two (256) -> shift instead of divide.
    int log2_q = 0;
    while ((1 << log2_q) < quads_per_edge) log2_q++;

    int total_quads = in_sizes[0] / 4;            // 12.8M

    int threads = 256;
    int blocks = (total_quads + threads - 1) / threads;

    plt_kernel<<<blocks, threads>>>((const float4*)x, (const float4*)W,
                                    (const float2*)b, (float4*)d_out,
                                    total_quads, log2_q);
}

// round 2
// speedup vs baseline: 1.0633x; 1.0633x over previous
#include <cuda_runtime.h>

// out[e,b,o] = sum_n x[e,b,n] * W[e,o,n] + b[e,o]
// E=50000, B=512, N=2, O=2. Pure HBM streaming problem (~411 MB, 205 MFLOP).
//
// R2: 4x unrolled streaming — each thread handles 4 independent float4s,
// front-batched, to raise per-warp MLP (outstanding DRAM sectors) and
// amortize the W/b broadcast loads. A 256-thread block covers 1024 quads
// = exactly 4 edges (edge-aligned), so W/b loads are warp-uniform.

#define UNROLL 4

__global__ void __launch_bounds__(256) plt_kernel(
        const float4* __restrict__ x4,
        const float4* __restrict__ W4,
        const float2* __restrict__ b2,
        float4* __restrict__ out4,
        int total_quads,
        int log2_quads_per_edge) {
    int base = blockIdx.x * (blockDim.x * UNROLL) + threadIdx.x;

    int idx[UNROLL];
    bool ok[UNROLL];
    float4 xv[UNROLL];

    // Front-batched x loads: 4 independent LDG.128 issued back-to-back.
    #pragma unroll
    for (int k = 0; k < UNROLL; k++) {
        idx[k] = base + k * 256;
        ok[k] = idx[k] < total_quads;
        if (ok[k]) xv[k] = __ldg(x4 + idx[k]);
    }

    // Per-chunk edge params (warp-uniform broadcast loads).
    float4 wv[UNROLL];
    float2 bv[UNROLL];
    #pragma unroll
    for (int k = 0; k < UNROLL; k++) {
        if (ok[k]) {
            int e = idx[k] >> log2_quads_per_edge;
            wv[k] = __ldg(W4 + e);
            bv[k] = __ldg(b2 + e);
        }
    }

    #pragma unroll
    for (int k = 0; k < UNROLL; k++) {
        if (ok[k]) {
            float4 o;
            o.x = fmaf(xv[k].x, wv[k].x, fmaf(xv[k].y, wv[k].y, bv[k].x));
            o.y = fmaf(xv[k].x, wv[k].z, fmaf(xv[k].y, wv[k].w, bv[k].y));
            o.z = fmaf(xv[k].z, wv[k].x, fmaf(xv[k].w, wv[k].y, bv[k].x));
            o.w = fmaf(xv[k].z, wv[k].z, fmaf(xv[k].w, wv[k].w, bv[k].y));
            out4[idx[k]] = o;
        }
    }
}

extern "C" void kernel_launch(void* const* d_in, const int* in_sizes, int n_in,
                              void* d_out, int out_size) {
    const float* x = (const float*)d_in[0];   // [E, B, N]
    const float* W = (const float*)d_in[1];   // [E, O, N]
    const float* b = (const float*)d_in[2];   // [E, O]

    int E = in_sizes[2] / 2;                  // 50000
    int per_edge = in_sizes[0] / E;           // B*N = 1024 floats
    int quads_per_edge = per_edge / 4;        // 256
    int log2_q = 0;
    while ((1 << log2_q) < quads_per_edge) log2_q++;

    int total_quads = in_sizes[0] / 4;        // 12.8M

    int threads = 256;
    int quads_per_block = threads * UNROLL;   // 1024
    int blocks = (total_quads + quads_per_block - 1) / quads_per_block;  // 12500

    plt_kernel<<<blocks, threads>>>((const float4*)x, (const float4*)W,
                                    (const float2*)b, (float4*)d_out,
                                    total_quads, log2_q);
}